// round 15
// baseline (speedup 1.0000x reference)
#include <cuda_runtime.h>
#include <cuda_fp16.h>

// LightGCN: 3 propagation layers, N=100000, d=64, E=1250000.
// R15: R10/R14 proven core (8 threads/node, uint4 fp16 gathers, 8 edges/iter,
// natural order, scalar k_build@256) + grid-stride layer kernels with an
// exact-fill grid (148 SMs x 6 resident blocks = 888): removes the 0.52-wave
// quantization tail (grid was 3125 blocks = 3.52 waves). Blocks sweep
// consecutive 32-node chunks so ELL index streaming locality is preserved.
//
// __device__ symbols are NEVER passed as kernel args from host (host shadow
// + ATS on GB300 makes that silently wrong) — resolved device-side.

#define N_NODES 100000
#define N_EDGES 1250000
#define DIM     64
#define DIM4    16
#define ELLW    64     // max in-degree tracked; P(overflow) ~ 1e-28
#define LGRID   888    // 148 SMs * 6 resident blocks (regs=40, 256 thr)

// Scratch (__device__ globals; no allocation allowed)
__device__ int   g_cursor[N_NODES];               // in-degree
__device__ float g_dis[N_NODES];
__device__ int   g_ell[N_NODES * ELLW + 8];       // +8: unconditional prefetch
__device__ uint4 g_zA[(N_NODES + 1) * 8];         // fp16 z, 64 halves/row
__device__ uint4 g_zB[(N_NODES + 1) * 8];         // row nN = zero (dummy)
__device__ int   g_is64;

// ---------------------------------------------------------------------------
// Zero cursors (int4-vectorized) + dtype detect + ELL tail pad.
__global__ void k_init(const void* ei, int nE, int nN) {
    int i = blockIdx.x * blockDim.x + threadIdx.x;
    int nq = (nN + 3) >> 2;
    if (i < nq) {
        // N_NODES = 100000 is a multiple of 4: full int4 store is safe
        ((int4*)g_cursor)[i] = make_int4(0, 0, 0, 0);
    }
    if (i == 0) {
        const long long* p = (const long long*)ei;
        int ok64 = 1;
        int ns = (nE < 64) ? nE : 64;
        for (int s = 0; s < ns; s++) {
            long long v = p[s];
            if (v < 0 || v >= nN) { ok64 = 0; break; }
        }
        g_is64 = ok64;
        #pragma unroll
        for (int k = 0; k < 8; k++) g_ell[(long long)nN * ELLW + k] = nN;
    }
}

// ---------------------------------------------------------------------------
// Edge pass (1 edge/thread): decode (dtype-adaptive), validate, bucket.
__global__ void k_build(const void* __restrict__ ei, int nE, int nN) {
    int e = blockIdx.x * blockDim.x + threadIdx.x;
    if (e >= nE) return;
    long long r64, c64;
    if (g_is64) {
        const long long* p = (const long long*)ei;
        r64 = p[e]; c64 = p[nE + e];
    } else {
        const int* p = (const int*)ei;
        r64 = p[e]; c64 = p[nE + e];
    }
    if (r64 < 0 || r64 >= nN || c64 < 0 || c64 >= nN) return;
    int c = (int)c64;
    int pos = atomicAdd(&g_cursor[c], 1);
    if (pos < ELLW) g_ell[c * ELLW + pos] = (int)r64;
}

// ---------------------------------------------------------------------------
// Pack 8 fp32 -> uint4 of 4 half2
__device__ __forceinline__ uint4 pack8(const float* v) {
    __half2 h0 = __floats2half2_rn(v[0], v[1]);
    __half2 h1 = __floats2half2_rn(v[2], v[3]);
    __half2 h2 = __floats2half2_rn(v[4], v[5]);
    __half2 h3 = __floats2half2_rn(v[6], v[7]);
    uint4 u;
    u.x = *(unsigned*)&h0; u.y = *(unsigned*)&h1;
    u.z = *(unsigned*)&h2; u.w = *(unsigned*)&h3;
    return u;
}

// Unpack uint4 of 4 half2 -> accumulate into 8 fp32
__device__ __forceinline__ void acc8(float* s, uint4 u) {
    float2 f0 = __half22float2(*(__half2*)&u.x);
    float2 f1 = __half22float2(*(__half2*)&u.y);
    float2 f2 = __half22float2(*(__half2*)&u.z);
    float2 f3 = __half22float2(*(__half2*)&u.w);
    s[0] += f0.x; s[1] += f0.y; s[2] += f1.x; s[3] += f1.y;
    s[4] += f2.x; s[5] += f2.y; s[6] += f3.x; s[7] += f3.y;
}

// ---------------------------------------------------------------------------
// dis = rsqrt(deg); z0 = fp16(dis .* emb); pad ELL to multiple of 8 with the
// dummy row nN; zero the dummy row in both z buffers. 8 threads/node.
__global__ void k_z0(const float4* __restrict__ emb, int nN) {
    int t = blockIdx.x * blockDim.x + threadIdx.x;
    int n = t >> 3;
    int c = t & 7;
    if (n > nN) return;
    if (n == nN) {   // dummy zero row
        uint4 z = make_uint4(0, 0, 0, 0);
        g_zA[n * 8 + c] = z;
        g_zB[n * 8 + c] = z;
        return;
    }
    int d = g_cursor[n];
    float dis = (d > 0) ? rsqrtf((float)d) : 0.f;
    if (c == 0) {
        g_dis[n] = dis;
        int cnt = (d < ELLW) ? d : ELLW;
        int pad = (8 - (cnt & 7)) & 7;           // cnt+pad <= 64 always
        for (int k = 0; k < pad; k++) g_ell[n * ELLW + cnt + k] = nN;
    }
    float4 a0 = __ldg(&emb[n * DIM4 + c * 2]);
    float4 a1 = __ldg(&emb[n * DIM4 + c * 2 + 1]);
    float v[8] = { dis * a0.x, dis * a0.y, dis * a0.z, dis * a0.w,
                   dis * a1.x, dis * a1.y, dis * a1.z, dis * a1.w };
    g_zA[n * 8 + c] = pack8(v);
}

// ---------------------------------------------------------------------------
// One layer as gather-reduce: 8 threads/node, 8 dims each, 8 edges/iter.
// Grid-stride over consecutive 32-node chunks (exact-fill grid, no wave tail).
// stage 0: zA->zB (z1); stage 1: zB->zA (z2);
// stage 2: gather zA(z2) -> out = 0.25*(emb + (z1+z2)*sqrt(deg) + dis*s)
__global__ void __launch_bounds__(256)
k_layer(const float4* __restrict__ emb, float4* __restrict__ out,
        int stage, int nN) {
    const uint4* src = (stage == 1) ? g_zB : g_zA;
    int lane_n = threadIdx.x >> 3;      // 0..31 node-within-chunk
    int c      = threadIdx.x & 7;

    for (int n0 = blockIdx.x * 32; n0 < nN; n0 += gridDim.x * 32) {
        int n = n0 + lane_n;
        if (n >= nN) continue;

        int degc = g_cursor[n];
        int deg = (degc < ELLW) ? degc : ELLW;
        int npair = (deg + 7) >> 3;           // 8-edge groups (padded)
        const int4* lst = (const int4*)&g_ell[n * ELLW];

        float s[8] = {0.f, 0.f, 0.f, 0.f, 0.f, 0.f, 0.f, 0.f};
        if (npair > 0) {
            int4 ra = __ldg(&lst[0]);
            int4 rb = __ldg(&lst[1]);
            for (int p = 0; p < npair; p++) {
                int4 na = __ldg(&lst[2 * p + 2]);   // unconditional (padded)
                int4 nb = __ldg(&lst[2 * p + 3]);
                uint4 v0 = __ldg(&src[ra.x * 8 + c]);
                uint4 v1 = __ldg(&src[ra.y * 8 + c]);
                uint4 v2 = __ldg(&src[ra.z * 8 + c]);
                uint4 v3 = __ldg(&src[ra.w * 8 + c]);
                uint4 v4 = __ldg(&src[rb.x * 8 + c]);
                uint4 v5 = __ldg(&src[rb.y * 8 + c]);
                uint4 v6 = __ldg(&src[rb.z * 8 + c]);
                uint4 v7 = __ldg(&src[rb.w * 8 + c]);
                acc8(s, v0); acc8(s, v1); acc8(s, v2); acc8(s, v3);
                acc8(s, v4); acc8(s, v5); acc8(s, v6); acc8(s, v7);
                ra = na; rb = nb;
            }
        }

        float dis = g_dis[n];
        int idx = n * 8 + c;

        if (stage != 2) {
            float d2 = dis * dis;
            float z[8];
            #pragma unroll
            for (int k = 0; k < 8; k++) z[k] = d2 * s[k];
            uint4 u = pack8(z);
            if (stage == 0) g_zB[idx] = u;
            else            g_zA[idx] = u;
        } else {
            float sqd = (degc > 0) ? sqrtf((float)degc) : 0.f;
            float4 a0 = __ldg(&emb[n * DIM4 + c * 2]);
            float4 a1 = __ldg(&emb[n * DIM4 + c * 2 + 1]);
            float zsum[8] = {0.f, 0.f, 0.f, 0.f, 0.f, 0.f, 0.f, 0.f};
            acc8(zsum, g_zB[idx]);   // z1
            acc8(zsum, g_zA[idx]);   // z2
            float4 o0, o1;
            o0.x = (a0.x + zsum[0] * sqd + dis * s[0]) * 0.25f;
            o0.y = (a0.y + zsum[1] * sqd + dis * s[1]) * 0.25f;
            o0.z = (a0.z + zsum[2] * sqd + dis * s[2]) * 0.25f;
            o0.w = (a0.w + zsum[3] * sqd + dis * s[3]) * 0.25f;
            o1.x = (a1.x + zsum[4] * sqd + dis * s[4]) * 0.25f;
            o1.y = (a1.y + zsum[5] * sqd + dis * s[5]) * 0.25f;
            o1.z = (a1.z + zsum[6] * sqd + dis * s[6]) * 0.25f;
            o1.w = (a1.w + zsum[7] * sqd + dis * s[7]) * 0.25f;
            out[n * DIM4 + c * 2]     = o0;
            out[n * DIM4 + c * 2 + 1] = o1;
        }
    }
}

// ---------------------------------------------------------------------------
extern "C" void kernel_launch(void* const* d_in, const int* in_sizes, int n_in,
                              void* d_out, int out_size) {
    // Identify inputs by SIZE: emb has 6.4M elements, edge_index has 2.5M.
    int a = 0, b = (n_in >= 2) ? 1 : 0;
    if (n_in >= 2 && in_sizes[1] > in_sizes[0]) { a = 1; b = 0; }
    const float* emb = (const float*)d_in[a];
    const void*  ei  = d_in[b];
    int emb_elems = in_sizes[a];
    int ei_elems  = in_sizes[b];

    float* out = (float*)d_out;

    int nN = emb_elems / DIM;   // 100000
    int nE = ei_elems / 2;      // 1250000
    if (nN > N_NODES) nN = N_NODES;
    if (nE > N_EDGES) nE = N_EDGES;

    const int TPB = 256;
    int nblkI = ((nN + 3) / 4 + TPB - 1) / TPB;
    int nblkE = (nE + TPB - 1) / TPB;

    // Setup: 3 kernels
    k_init<<<nblkI, TPB>>>(ei, nE, nN);
    k_build<<<nblkE, TPB>>>(ei, nE, nN);
    {
        long long zthreads = (long long)(nN + 1) * 8;
        int zblocks = (int)((zthreads + TPB - 1) / TPB);
        k_z0<<<zblocks, TPB>>>((const float4*)emb, nN);
    }

    // 3 gather layers: grid-stride, exact-fill grid (no wave tail)
    k_layer<<<LGRID, TPB>>>((const float4*)emb, (float4*)out, 0, nN);
    k_layer<<<LGRID, TPB>>>((const float4*)emb, (float4*)out, 1, nN);
    k_layer<<<LGRID, TPB>>>((const float4*)emb, (float4*)out, 2, nN);
}

// round 16
// speedup vs baseline: 1.0451x; 1.0451x over previous
#include <cuda_runtime.h>
#include <cuda_fp16.h>

// LightGCN: 3 propagation layers, N=100000, d=64, E=1250000.
// R16: setup reverted byte-exact to R10 (best measured: scalar cursor zero,
// 1-edge/thread k_build@256 — every later setup tweak was neutral/negative).
// k_layer: R10 geometry (8 t/node, uint4 fp16 gathers, 8 edges/iter, natural
// order, grid 3125) with the index software-pipeline dropped (the 8 feature
// loads already give MLP) and the freed regs spent on __launch_bounds__(256,8)
// -> 8 resident blocks/SM (100% theoretical occupancy vs 75%) to cover the
// exposed L2 latency that binds this kernel.
//
// __device__ symbols are NEVER passed as kernel args from host (host shadow
// + ATS on GB300 makes that silently wrong) — resolved device-side.

#define N_NODES 100000
#define N_EDGES 1250000
#define DIM     64
#define DIM4    16
#define ELLW    64     // max in-degree tracked; P(overflow) ~ 1e-28

// Scratch (__device__ globals; no allocation allowed)
__device__ int   g_cursor[N_NODES];               // in-degree
__device__ float g_dis[N_NODES];
__device__ int   g_ell[N_NODES * ELLW + 8];       // +8: tail safety
__device__ uint4 g_zA[(N_NODES + 1) * 8];         // fp16 z, 64 halves/row
__device__ uint4 g_zB[(N_NODES + 1) * 8];         // row nN = zero (dummy)
__device__ int   g_is64;

// ---------------------------------------------------------------------------
// Zero cursors + dtype detect + ELL tail pad (exact R10 form).
__global__ void k_init(const void* ei, int nE, int nN) {
    int i = blockIdx.x * blockDim.x + threadIdx.x;
    if (i < nN) g_cursor[i] = 0;
    if (i == 0) {
        const long long* p = (const long long*)ei;
        int ok64 = 1;
        int ns = (nE < 64) ? nE : 64;
        for (int s = 0; s < ns; s++) {
            long long v = p[s];
            if (v < 0 || v >= nN) { ok64 = 0; break; }
        }
        g_is64 = ok64;
        #pragma unroll
        for (int k = 0; k < 8; k++) g_ell[(long long)nN * ELLW + k] = nN;
    }
}

// ---------------------------------------------------------------------------
// Edge pass (1 edge/thread): decode (dtype-adaptive), validate, bucket.
__global__ void k_build(const void* __restrict__ ei, int nE, int nN) {
    int e = blockIdx.x * blockDim.x + threadIdx.x;
    if (e >= nE) return;
    long long r64, c64;
    if (g_is64) {
        const long long* p = (const long long*)ei;
        r64 = p[e]; c64 = p[nE + e];
    } else {
        const int* p = (const int*)ei;
        r64 = p[e]; c64 = p[nE + e];
    }
    if (r64 < 0 || r64 >= nN || c64 < 0 || c64 >= nN) return;
    int c = (int)c64;
    int pos = atomicAdd(&g_cursor[c], 1);
    if (pos < ELLW) g_ell[c * ELLW + pos] = (int)r64;
}

// ---------------------------------------------------------------------------
// Pack 8 fp32 -> uint4 of 4 half2
__device__ __forceinline__ uint4 pack8(const float* v) {
    __half2 h0 = __floats2half2_rn(v[0], v[1]);
    __half2 h1 = __floats2half2_rn(v[2], v[3]);
    __half2 h2 = __floats2half2_rn(v[4], v[5]);
    __half2 h3 = __floats2half2_rn(v[6], v[7]);
    uint4 u;
    u.x = *(unsigned*)&h0; u.y = *(unsigned*)&h1;
    u.z = *(unsigned*)&h2; u.w = *(unsigned*)&h3;
    return u;
}

// Unpack uint4 of 4 half2 -> accumulate into 8 fp32
__device__ __forceinline__ void acc8(float* s, uint4 u) {
    float2 f0 = __half22float2(*(__half2*)&u.x);
    float2 f1 = __half22float2(*(__half2*)&u.y);
    float2 f2 = __half22float2(*(__half2*)&u.z);
    float2 f3 = __half22float2(*(__half2*)&u.w);
    s[0] += f0.x; s[1] += f0.y; s[2] += f1.x; s[3] += f1.y;
    s[4] += f2.x; s[5] += f2.y; s[6] += f3.x; s[7] += f3.y;
}

// ---------------------------------------------------------------------------
// dis = rsqrt(deg); z0 = fp16(dis .* emb); pad ELL to multiple of 8 with the
// dummy row nN; zero the dummy row in both z buffers. 8 threads/node.
__global__ void k_z0(const float4* __restrict__ emb, int nN) {
    int t = blockIdx.x * blockDim.x + threadIdx.x;
    int n = t >> 3;
    int c = t & 7;
    if (n > nN) return;
    if (n == nN) {   // dummy zero row
        uint4 z = make_uint4(0, 0, 0, 0);
        g_zA[n * 8 + c] = z;
        g_zB[n * 8 + c] = z;
        return;
    }
    int d = g_cursor[n];
    float dis = (d > 0) ? rsqrtf((float)d) : 0.f;
    if (c == 0) {
        g_dis[n] = dis;
        int cnt = (d < ELLW) ? d : ELLW;
        int pad = (8 - (cnt & 7)) & 7;           // cnt+pad <= 64 always
        for (int k = 0; k < pad; k++) g_ell[n * ELLW + cnt + k] = nN;
    }
    float4 a0 = __ldg(&emb[n * DIM4 + c * 2]);
    float4 a1 = __ldg(&emb[n * DIM4 + c * 2 + 1]);
    float v[8] = { dis * a0.x, dis * a0.y, dis * a0.z, dis * a0.w,
                   dis * a1.x, dis * a1.y, dis * a1.z, dis * a1.w };
    g_zA[n * 8 + c] = pack8(v);
}

// ---------------------------------------------------------------------------
// One layer as gather-reduce: 8 threads/node, 8 dims each, 8 edges/iter.
// No idx software-pipeline; regs spent on occupancy (8 blocks/SM).
// stage 0: zA->zB (z1); stage 1: zB->zA (z2);
// stage 2: gather zA(z2) -> out = 0.25*(emb + (z1+z2)*sqrt(deg) + dis*s)
__global__ void __launch_bounds__(256, 8)
k_layer(const float4* __restrict__ emb, float4* __restrict__ out,
        int stage, int nN) {
    int t = blockIdx.x * blockDim.x + threadIdx.x;
    int n = t >> 3;
    int c = t & 7;
    if (n >= nN) return;

    const uint4* src = (stage == 1) ? g_zB : g_zA;

    int degc = g_cursor[n];
    int deg = (degc < ELLW) ? degc : ELLW;
    int npair = (deg + 7) >> 3;               // 8-edge groups (padded in k_z0)
    const int4* lst = (const int4*)&g_ell[n * ELLW];

    float s[8] = {0.f, 0.f, 0.f, 0.f, 0.f, 0.f, 0.f, 0.f};
    for (int p = 0; p < npair; p++) {
        int4 ra = __ldg(&lst[2 * p]);
        int4 rb = __ldg(&lst[2 * p + 1]);
        uint4 v0 = __ldg(&src[ra.x * 8 + c]);
        uint4 v1 = __ldg(&src[ra.y * 8 + c]);
        uint4 v2 = __ldg(&src[ra.z * 8 + c]);
        uint4 v3 = __ldg(&src[ra.w * 8 + c]);
        uint4 v4 = __ldg(&src[rb.x * 8 + c]);
        uint4 v5 = __ldg(&src[rb.y * 8 + c]);
        uint4 v6 = __ldg(&src[rb.z * 8 + c]);
        uint4 v7 = __ldg(&src[rb.w * 8 + c]);
        acc8(s, v0); acc8(s, v1); acc8(s, v2); acc8(s, v3);
        acc8(s, v4); acc8(s, v5); acc8(s, v6); acc8(s, v7);
    }

    float dis = g_dis[n];
    int idx = n * 8 + c;

    if (stage != 2) {
        float d2 = dis * dis;
        float z[8];
        #pragma unroll
        for (int k = 0; k < 8; k++) z[k] = d2 * s[k];
        uint4 u = pack8(z);
        if (stage == 0) g_zB[idx] = u;
        else            g_zA[idx] = u;
    } else {
        float sqd = (degc > 0) ? sqrtf((float)degc) : 0.f;
        float4 a0 = __ldg(&emb[n * DIM4 + c * 2]);
        float4 a1 = __ldg(&emb[n * DIM4 + c * 2 + 1]);
        float zsum[8] = {0.f, 0.f, 0.f, 0.f, 0.f, 0.f, 0.f, 0.f};
        acc8(zsum, g_zB[idx]);   // z1
        acc8(zsum, g_zA[idx]);   // z2
        float4 o0, o1;
        o0.x = (a0.x + zsum[0] * sqd + dis * s[0]) * 0.25f;
        o0.y = (a0.y + zsum[1] * sqd + dis * s[1]) * 0.25f;
        o0.z = (a0.z + zsum[2] * sqd + dis * s[2]) * 0.25f;
        o0.w = (a0.w + zsum[3] * sqd + dis * s[3]) * 0.25f;
        o1.x = (a1.x + zsum[4] * sqd + dis * s[4]) * 0.25f;
        o1.y = (a1.y + zsum[5] * sqd + dis * s[5]) * 0.25f;
        o1.z = (a1.z + zsum[6] * sqd + dis * s[6]) * 0.25f;
        o1.w = (a1.w + zsum[7] * sqd + dis * s[7]) * 0.25f;
        out[n * DIM4 + c * 2]     = o0;
        out[n * DIM4 + c * 2 + 1] = o1;
    }
}

// ---------------------------------------------------------------------------
extern "C" void kernel_launch(void* const* d_in, const int* in_sizes, int n_in,
                              void* d_out, int out_size) {
    // Identify inputs by SIZE: emb has 6.4M elements, edge_index has 2.5M.
    int a = 0, b = (n_in >= 2) ? 1 : 0;
    if (n_in >= 2 && in_sizes[1] > in_sizes[0]) { a = 1; b = 0; }
    const float* emb = (const float*)d_in[a];
    const void*  ei  = d_in[b];
    int emb_elems = in_sizes[a];
    int ei_elems  = in_sizes[b];

    float* out = (float*)d_out;

    int nN = emb_elems / DIM;   // 100000
    int nE = ei_elems / 2;      // 1250000
    if (nN > N_NODES) nN = N_NODES;
    if (nE > N_EDGES) nE = N_EDGES;

    const int TPB = 256;
    int nblkN = (nN + TPB - 1) / TPB;
    int nblkE = (nE + TPB - 1) / TPB;

    // Setup: 3 kernels (exact R10)
    k_init<<<nblkN, TPB>>>(ei, nE, nN);
    k_build<<<nblkE, TPB>>>(ei, nE, nN);
    {
        long long zthreads = (long long)(nN + 1) * 8;
        int zblocks = (int)((zthreads + TPB - 1) / TPB);
        k_z0<<<zblocks, TPB>>>((const float4*)emb, nN);
    }

    // 3 gather layers (8 threads per node); layer 3 fuses the final average
    long long nthreads = (long long)nN * 8;
    int lblocks = (int)((nthreads + TPB - 1) / TPB);
    k_layer<<<lblocks, TPB>>>((const float4*)emb, (float4*)out, 0, nN);
    k_layer<<<lblocks, TPB>>>((const float4*)emb, (float4*)out, 1, nN);
    k_layer<<<lblocks, TPB>>>((const float4*)emb, (float4*)out, 2, nN);
}